// round 15
// baseline (speedup 1.0000x reference)
#include <cuda_runtime.h>
#include <cuda_fp16.h>
#include <math.h>
#include <stdint.h>

#define BB 4
#define CC 64
#define MH 18
#define HH 128
#define WW 128
#define NN 9
#define HWX (HH*WW)

typedef unsigned long long ull;

// ---------------- scratch (static __device__, zero-initialized) ----------------
__device__ float  g_update[BB*MH*HH*WW];
__device__ float  g_m     [BB*NN*HH*WW];
__device__ float  g_candx [BB*MH*HH*WW];
__device__ __half g_xTh   [BB*130*130*CC];   // padded NHWC x (fp16); border stays 0
__device__ __half g_preh  [BB*130*130*24];   // padded NHWC pre (fp16, 18 used)
__device__ __half g_rgh   [BB*130*130*24];   // padded NHWC rgoff (fp16, 18 used)

__device__ __forceinline__ float sigf(float x) { return 1.f/(1.f + __expf(-x)); }

// ---- f32x2 helpers ----
__device__ __forceinline__ ull ffma2(ull a, ull b, ull c) {
    ull d; asm("fma.rn.f32x2 %0,%1,%2,%3;" : "=l"(d) : "l"(a), "l"(b), "l"(c)); return d;
}
__device__ __forceinline__ ull fmul2(ull a, ull b) {
    ull d; asm("mul.rn.f32x2 %0,%1,%2;" : "=l"(d) : "l"(a), "l"(b)); return d;
}
__device__ __forceinline__ ull dup2(float v) {
    ull d; asm("mov.b64 %0,{%1,%1};" : "=l"(d) : "f"(v)); return d;
}
__device__ __forceinline__ void unpack2(ull p, float& lo, float& hi) {
    asm("mov.b64 {%0,%1},%2;" : "=f"(lo), "=f"(hi) : "l"(p));
}
__device__ __forceinline__ uint32_t smaddr(const void* p) {
    return (uint32_t)__cvta_generic_to_shared(p);
}

// ---------------- kernel: NCHW fp32 x -> padded NHWC fp16 (interior) ----------------
__global__ void k_pad(const float* __restrict__ x) {
    __shared__ float sm[64][33];
    int jb = blockIdx.x, i0 = blockIdx.y, b = blockIdx.z;
    int tx = threadIdx.x, ty = threadIdx.y;
    int jcol = jb*32 + tx;
    for (int c = ty; c < 64; c += 8)
        sm[c][tx] = x[((b*CC + c)*HH + i0)*WW + jcol];
    __syncthreads();
    for (int jj = ty; jj < 32; jj += 8) {
        int base = ((b*130 + (i0+1))*130 + (jb*32 + jj + 1))*64;
        g_xTh[base + tx]      = __float2half_rn(sm[tx][jj]);
        g_xTh[base + 32 + tx] = __float2half_rn(sm[32 + tx][jj]);
    }
}

// ---------------- kernel: NCHW fp32 pre -> padded NHWC fp16 (interior) ----------------
__global__ void k_padp(const float* __restrict__ pre) {
    __shared__ float sm[18][129];
    int h = blockIdx.x, b = blockIdx.y;
    int t = threadIdx.x;
    #pragma unroll
    for (int c = 0; c < 18; ++c)
        sm[c][t] = pre[((b*MH + c)*HH + h)*WW + t];
    __syncthreads();
    __half* dst = g_preh + (size_t)((b*130 + h + 1)*130 + t + 1)*24;
    #pragma unroll
    for (int c = 0; c < 18; c += 2) {
        __half2 hh = __floats2half2_rn(sm[c][t], sm[c+1][t]);
        *reinterpret_cast<__half2*>(dst + c) = hh;
    }
}

// ====== shared HMMA conv geometry ======
#define PIN 104
#define SIN_ROWS 198
#define SIN_B (SIN_ROWS*PIN*2)
#define WPP 872
#define SO_PITCH 68
#define SO_B (64*SO_PITCH*4)
#define NTILES (BB*HH*2)

// ================= K1: upd + rst + wg + cand_x convs via HMMA =================
#define W1_OC 64
#define K1_SO_OFF (SIN_B + W1_OC*WPP*2)
#define K1_RG_OFF (K1_SO_OFF + SO_B)
#define K1_SMEM (K1_RG_OFF + 64*24*2)
#define K1_SLOTS 9

__global__ void __launch_bounds__(256, 1) k1_gates(
    const float* __restrict__ pre,
    const float* __restrict__ uw, const float* __restrict__ ub,
    const float* __restrict__ rw, const float* __restrict__ rb,
    const float* __restrict__ ww, const float* __restrict__ wb,
    const float* __restrict__ ow)
{
    extern __shared__ char shb[];
    __half* sIn = reinterpret_cast<__half*>(shb);
    __half* Wp  = reinterpret_cast<__half*>(shb + SIN_B);
    float*  so  = reinterpret_cast<float*>(shb + K1_SO_OFF);
    __half* sRg = reinterpret_cast<__half*>(shb + K1_RG_OFF);

    int t = threadIdx.x;
    int lane = t & 31, warp = t >> 5;

    for (int i = t; i < SIN_ROWS*PIN/8; i += 256)
        reinterpret_cast<uint4*>(sIn)[i] = make_uint4(0,0,0,0);
    for (int i = t; i < W1_OC*WPP/8; i += 256)
        reinterpret_cast<uint4*>(Wp)[i] = make_uint4(0,0,0,0);
    for (int i = t; i < 64*24/8; i += 256)
        reinterpret_cast<uint4*>(sRg)[i] = make_uint4(0,0,0,0);
    __syncthreads();
    for (int i = t; i < 18*738; i += 256) {
        int oc = i / 738, r = i % 738, ic = r / 9, pos = r % 9;
        Wp[oc*WPP + pos*96 + ic]        = __float2half_rn(uw[i]);
        Wp[(18 + oc)*WPP + pos*96 + ic] = __float2half_rn(rw[i]);
    }
    for (int i = t; i < 9*576; i += 256) {
        int oc = i / 576, r = i % 576, ic = r / 9, pos = r % 9;
        Wp[(36 + oc)*WPP + pos*96 + ic] = __float2half_rn(ww[i]);
    }
    for (int i = t; i < 18*576; i += 256) {
        int oc = i / 576, r = i % 576, ic = r / 9, pos = r % 9;
        Wp[(45 + oc)*WPP + pos*96 + ic] = __float2half_rn(ow[oc*738 + ic*9 + pos]);
    }
    __syncthreads();

    int ssrc[K1_SLOTS], sdst[K1_SLOTS], skind[K1_SLOTS];
    #pragma unroll
    for (int s = 0; s < K1_SLOTS; ++s) {
        int e = t + s*256;
        if (e < 2178) {
            int r = e / 11, u = e % 11;
            int crow = r / 66, col = r % 66;
            if (u < 8) {
                skind[s] = 0;
                ssrc[s] = (crow*130 + col)*64 + u*8;
                sdst[s] = r*PIN + u*8;
            } else {
                skind[s] = 1;
                ssrc[s] = (crow*130 + col)*24 + (u - 8)*8;
                sdst[s] = r*PIN + 64 + (u - 8)*8;
            }
        } else skind[s] = -1;
    }

    {
        int tile = blockIdx.x;
        int b = tile >> 8, rem = tile & 255;
        int h = rem >> 1, w0 = (rem & 1) << 6;
        const __half* xb = g_xTh  + (size_t)((b*130 + h)*130 + w0)*64;
        const __half* pb = g_preh + (size_t)((b*130 + h)*130 + w0)*24;
        #pragma unroll
        for (int s = 0; s < K1_SLOTS; ++s) {
            if (skind[s] == 0)
                *reinterpret_cast<uint4*>(sIn + sdst[s]) =
                    *reinterpret_cast<const uint4*>(xb + ssrc[s]);
            else if (skind[s] == 1)
                *reinterpret_cast<uint4*>(sIn + sdst[s]) =
                    *reinterpret_cast<const uint4*>(pb + ssrc[s]);
        }
    }
    __syncthreads();

    int wp = warp & 3, wo = warp >> 2;
    int px0 = wp * 16, oc0 = wo * 32;
    uint32_t aBase = smaddr(sIn) + (((px0 + (lane & 15))*PIN) + (lane >> 4)*8)*2;
    uint32_t bBase = smaddr(Wp) + ((oc0 + (lane & 7) + ((lane >> 4) & 1)*8)*WPP)*2
                     + ((lane >> 3) & 1)*16;
    int gid = lane >> 2, tig = lane & 3;

    for (int tile = blockIdx.x; tile < NTILES; tile += gridDim.x) {
        int b = tile >> 8;
        int rem = tile & 255;
        int h  = rem >> 1;
        int w0 = (rem & 1) << 6;

        int nxt = tile + gridDim.x;
        bool hasNext = nxt < NTILES;
        uint4 pf[K1_SLOTS];
        if (hasNext) {
            int b2 = nxt >> 8, rem2 = nxt & 255;
            int h2 = rem2 >> 1, w02 = (rem2 & 1) << 6;
            const __half* xb2 = g_xTh  + (size_t)((b2*130 + h2)*130 + w02)*64;
            const __half* pb2 = g_preh + (size_t)((b2*130 + h2)*130 + w02)*24;
            #pragma unroll
            for (int s = 0; s < K1_SLOTS; ++s) {
                if (skind[s] == 0)
                    pf[s] = *reinterpret_cast<const uint4*>(xb2 + ssrc[s]);
                else if (skind[s] == 1)
                    pf[s] = *reinterpret_cast<const uint4*>(pb2 + ssrc[s]);
            }
        }

        float d[4][4];
        #pragma unroll
        for (int i = 0; i < 4; ++i)
            #pragma unroll
            for (int j = 0; j < 4; ++j) d[i][j] = 0.f;

        #pragma unroll 1
        for (int pos = 0; pos < 9; ++pos) {
            int ki = pos / 3, kj = pos % 3;
            uint32_t aPos = aBase + (ki*66 + kj)*PIN*2;
            uint32_t bPos = bBase + pos*96*2;
            #pragma unroll
            for (int kk = 0; kk < 6; ++kk) {
                uint32_t a0,a1,a2,a3, b0,b1,b2,b3, b4,b5,b6,b7;
                asm volatile("ldmatrix.sync.aligned.m8n8.x4.shared.b16 {%0,%1,%2,%3},[%4];"
                    : "=r"(a0),"=r"(a1),"=r"(a2),"=r"(a3) : "r"(aPos + kk*32));
                asm volatile("ldmatrix.sync.aligned.m8n8.x4.shared.b16 {%0,%1,%2,%3},[%4];"
                    : "=r"(b0),"=r"(b1),"=r"(b2),"=r"(b3) : "r"(bPos + kk*32));
                asm volatile("ldmatrix.sync.aligned.m8n8.x4.shared.b16 {%0,%1,%2,%3},[%4];"
                    : "=r"(b4),"=r"(b5),"=r"(b6),"=r"(b7) : "r"(bPos + 16*WPP*2 + kk*32));
                asm volatile("mma.sync.aligned.m16n8k16.row.col.f32.f16.f16.f32 "
                    "{%0,%1,%2,%3},{%4,%5,%6,%7},{%8,%9},{%0,%1,%2,%3};"
                    : "+f"(d[0][0]),"+f"(d[0][1]),"+f"(d[0][2]),"+f"(d[0][3])
                    : "r"(a0),"r"(a1),"r"(a2),"r"(a3),"r"(b0),"r"(b1));
                asm volatile("mma.sync.aligned.m16n8k16.row.col.f32.f16.f16.f32 "
                    "{%0,%1,%2,%3},{%4,%5,%6,%7},{%8,%9},{%0,%1,%2,%3};"
                    : "+f"(d[1][0]),"+f"(d[1][1]),"+f"(d[1][2]),"+f"(d[1][3])
                    : "r"(a0),"r"(a1),"r"(a2),"r"(a3),"r"(b2),"r"(b3));
                asm volatile("mma.sync.aligned.m16n8k16.row.col.f32.f16.f16.f32 "
                    "{%0,%1,%2,%3},{%4,%5,%6,%7},{%8,%9},{%0,%1,%2,%3};"
                    : "+f"(d[2][0]),"+f"(d[2][1]),"+f"(d[2][2]),"+f"(d[2][3])
                    : "r"(a0),"r"(a1),"r"(a2),"r"(a3),"r"(b4),"r"(b5));
                asm volatile("mma.sync.aligned.m16n8k16.row.col.f32.f16.f16.f32 "
                    "{%0,%1,%2,%3},{%4,%5,%6,%7},{%8,%9},{%0,%1,%2,%3};"
                    : "+f"(d[3][0]),"+f"(d[3][1]),"+f"(d[3][2]),"+f"(d[3][3])
                    : "r"(a0),"r"(a1),"r"(a2),"r"(a3),"r"(b6),"r"(b7));
            }
        }

        #pragma unroll
        for (int nt = 0; nt < 4; ++nt) {
            int oc = oc0 + nt*8 + tig*2;
            int pr = px0 + gid;
            so[pr*SO_PITCH + oc]         = d[nt][0];
            so[pr*SO_PITCH + oc + 1]     = d[nt][1];
            so[(pr+8)*SO_PITCH + oc]     = d[nt][2];
            so[(pr+8)*SO_PITCH + oc + 1] = d[nt][3];
        }
        __syncthreads();

        if (hasNext) {
            #pragma unroll
            for (int s = 0; s < K1_SLOTS; ++s)
                if (skind[s] >= 0)
                    *reinterpret_cast<uint4*>(sIn + sdst[s]) = pf[s];
        }

        for (int i = t; i < 63*64; i += 256) {
            int oc = i >> 6, px = i & 63;
            float a = so[px*SO_PITCH + oc];
            if (oc < 18) {
                g_update[((b*MH + oc)*HH + h)*WW + w0 + px] = sigf(a + ub[oc]);
            } else if (oc < 36) {
                int o = oc - 18;
                int idx = ((b*MH + o)*HH + h)*WW + w0 + px;
                float rv = pre[idx] * sigf(a + rb[o]);
                sRg[px*24 + o] = __float2half_rn(rv);
            } else if (oc < 45) {
                int o = oc - 36;
                g_m[((b*NN + o)*HH + h)*WW + w0 + px] = sigf(a + wb[o]);
            } else {
                int o = oc - 45;
                g_candx[((b*MH + o)*HH + h)*WW + w0 + px] = a;
            }
        }
        __syncthreads();

        {
            __half* dst = g_rgh + (size_t)((b*130 + h + 1)*130 + (w0 + 1))*24;
            if (t < 192)
                reinterpret_cast<uint4*>(dst)[t] =
                    reinterpret_cast<const uint4*>(sRg)[t];
        }
    }
}

// ================= k_fused: cand_p conv + GRU combine + warp + regroup conv =================
#define KP 584
#define PIN2 40
#define SIN2_B (SIN_ROWS*PIN2*2)     /* 15840 */
#define WPP2 296
#define W2_OC 32
#define F_SW_OFF   0
#define F_SV_OFF   (64*KP*2)                 /* 74752  */
#define F_SIN2_OFF (F_SV_OFF + 64*KP*2)      /* 149504 */
#define F_WP2_OFF  (F_SIN2_OFF + SIN2_B)     /* 165344 */
#define F_SOFF_OFF (F_WP2_OFF + W2_OC*WPP2*2)/* 184288 */
#define F_SCR_OFF  (F_SOFF_OFF + 64*20*4)    /* 189408 */
#define F_SMEM     (F_SCR_OFF + 18432)       /* 207840 */
#define F_SLOTS 3

__global__ void __launch_bounds__(256, 1) k_fused(
    const float* __restrict__ pre, const float* __restrict__ mean,
    const float* __restrict__ ow, const float* __restrict__ ob,
    const float* __restrict__ Wc,
    float* __restrict__ out_off, float* __restrict__ out_mean,
    float* __restrict__ out)
{
    extern __shared__ char shb[];
    __half* sW   = reinterpret_cast<__half*>(shb + F_SW_OFF);
    __half* sv   = reinterpret_cast<__half*>(shb + F_SV_OFF);
    __half* sIn2 = reinterpret_cast<__half*>(shb + F_SIN2_OFF);
    __half* Wp2  = reinterpret_cast<__half*>(shb + F_WP2_OFF);
    float*  sOff = reinterpret_cast<float*>(shb + F_SOFF_OFF);   // [64 px][20]
    float*  so2  = reinterpret_cast<float*>(shb + F_SCR_OFF);    // [64][68]
    float4* wts  = reinterpret_cast<float4*>(shb + F_SCR_OFF);
    int4*   ads  = reinterpret_cast<int4*>(shb + F_SCR_OFF + 9216);
    float*  so   = reinterpret_cast<float*>(shb + F_SCR_OFF);    // [64][69]

    int t = threadIdx.x;
    int lane = t & 31, warp = t >> 5;

    // preamble: warp weights + k2 weights + zero sIn2
    for (int i = t; i < 64*576; i += 256) {
        int co = i / 576, r = i % 576;
        int ci = r / 9, n = r % 9;
        sW[co*KP + n*64 + ci] = __float2half_rn(Wc[i]);
    }
    for (int i = t; i < SIN_ROWS*PIN2/8; i += 256)
        reinterpret_cast<uint4*>(sIn2)[i] = make_uint4(0,0,0,0);
    for (int i = t; i < W2_OC*WPP2/8; i += 256)
        reinterpret_cast<uint4*>(Wp2)[i] = make_uint4(0,0,0,0);
    __syncthreads();
    for (int i = t; i < 18*162; i += 256) {
        int oc = i / 162, r = i % 162, icp = r / 9, pos = r % 9;
        Wp2[oc*WPP2 + pos*32 + icp] = __float2half_rn(ow[oc*738 + (64 + icp)*9 + pos]);
    }

    // k2 staging slot descriptors
    int ssrc[F_SLOTS], sdst[F_SLOTS];
    #pragma unroll
    for (int s = 0; s < F_SLOTS; ++s) {
        int e = t + s*256;
        if (e < 594) {
            int r = e / 3, u = e % 3;
            int crow = r / 66, col = r % 66;
            ssrc[s] = (crow*130 + col)*24 + u*8;
            sdst[s] = r*PIN2 + u*8;
        } else { ssrc[s] = -1; sdst[s] = 0; }
    }

    // stage first tile's rgoff
    {
        int tile = blockIdx.x;
        int b = tile >> 8, rem = tile & 255;
        int h = rem >> 1, w0 = (rem & 1) << 6;
        const __half* rb2 = g_rgh + (size_t)((b*130 + h)*130 + w0)*24;
        #pragma unroll
        for (int s = 0; s < F_SLOTS; ++s)
            if (ssrc[s] >= 0)
                *reinterpret_cast<uint4*>(sIn2 + sdst[s]) =
                    *reinterpret_cast<const uint4*>(rb2 + ssrc[s]);
    }
    __syncthreads();

    // k2 GEMM mapping
    int wp = warp & 3, wo = warp >> 2;
    int px0_2 = wp * 16, oc0_2 = wo * 16;
    uint32_t aBase2 = smaddr(sIn2) + (((px0_2 + (lane & 15))*PIN2) + (lane >> 4)*8)*2;
    uint32_t bBase2 = smaddr(Wp2) + ((oc0_2 + (lane & 7) + ((lane >> 4) & 1)*8)*WPP2)*2
                      + ((lane >> 3) & 1)*16;
    int gid = lane >> 2, tig = lane & 3;

    // warp GEMM mapping
    int px0w = (warp >> 1) * 16;
    int co0w = (warp & 1) * 32;
    uint32_t aAddr = smaddr(sv) + (((px0w + (lane & 15))*KP + (lane >> 4)*8) << 1);
    uint32_t bAddr0 = smaddr(sW) + (((co0w + (lane & 7) + (lane >> 4)*8)*KP
                                    + ((lane >> 3) & 1)*8) << 1);
    uint32_t bAddr1 = bAddr0 + 16*KP*2;
    int gg = lane >> 3;
    int cc8 = lane & 7;

    for (int tile = blockIdx.x; tile < NTILES; tile += gridDim.x) {
        int b = tile >> 8;
        int rem = tile & 255;
        int h  = rem >> 1;
        int w0 = (rem & 1) << 6;
        const __half* xh = g_xTh + (size_t)b*130*130*64;

        // prefetch next tile's rgoff staging
        int nxt = tile + gridDim.x;
        bool hasNext = nxt < NTILES;
        uint4 pf[F_SLOTS];
        if (hasNext) {
            int b2 = nxt >> 8, rem2 = nxt & 255;
            int h2 = rem2 >> 1, w02 = (rem2 & 1) << 6;
            const __half* rb2 = g_rgh + (size_t)((b2*130 + h2)*130 + w02)*24;
            #pragma unroll
            for (int s = 0; s < F_SLOTS; ++s)
                if (ssrc[s] >= 0)
                    pf[s] = *reinterpret_cast<const uint4*>(rb2 + ssrc[s]);
        }

        // ---- k2 GEMM (cand_p) ----
        float d2[2][4];
        #pragma unroll
        for (int i = 0; i < 2; ++i)
            #pragma unroll
            for (int j = 0; j < 4; ++j) d2[i][j] = 0.f;

        #pragma unroll 1
        for (int pos = 0; pos < 9; ++pos) {
            int ki = pos / 3, kj = pos % 3;
            uint32_t aPos = aBase2 + (ki*66 + kj)*PIN2*2;
            uint32_t bPos = bBase2 + pos*32*2;
            #pragma unroll
            for (int kk = 0; kk < 2; ++kk) {
                uint32_t a0,a1,a2,a3, b0,b1,b2,b3;
                asm volatile("ldmatrix.sync.aligned.m8n8.x4.shared.b16 {%0,%1,%2,%3},[%4];"
                    : "=r"(a0),"=r"(a1),"=r"(a2),"=r"(a3) : "r"(aPos + kk*32));
                asm volatile("ldmatrix.sync.aligned.m8n8.x4.shared.b16 {%0,%1,%2,%3},[%4];"
                    : "=r"(b0),"=r"(b1),"=r"(b2),"=r"(b3) : "r"(bPos + kk*32));
                asm volatile("mma.sync.aligned.m16n8k16.row.col.f32.f16.f16.f32 "
                    "{%0,%1,%2,%3},{%4,%5,%6,%7},{%8,%9},{%0,%1,%2,%3};"
                    : "+f"(d2[0][0]),"+f"(d2[0][1]),"+f"(d2[0][2]),"+f"(d2[0][3])
                    : "r"(a0),"r"(a1),"r"(a2),"r"(a3),"r"(b0),"r"(b1));
                asm volatile("mma.sync.aligned.m16n8k16.row.col.f32.f16.f16.f32 "
                    "{%0,%1,%2,%3},{%4,%5,%6,%7},{%8,%9},{%0,%1,%2,%3};"
                    : "+f"(d2[1][0]),"+f"(d2[1][1]),"+f"(d2[1][2]),"+f"(d2[1][3])
                    : "r"(a0),"r"(a1),"r"(a2),"r"(a3),"r"(b2),"r"(b3));
            }
        }

        #pragma unroll
        for (int nt = 0; nt < 2; ++nt) {
            int oc = oc0_2 + nt*8 + tig*2;
            int pr = px0_2 + gid;
            so2[pr*SO_PITCH + oc]         = d2[nt][0];
            so2[pr*SO_PITCH + oc + 1]     = d2[nt][1];
            so2[(pr+8)*SO_PITCH + oc]     = d2[nt][2];
            so2[(pr+8)*SO_PITCH + oc + 1] = d2[nt][3];
        }
        __syncthreads();

        // commit prefetched rgoff (sIn2 reads done)
        if (hasNext) {
            #pragma unroll
            for (int s = 0; s < F_SLOTS; ++s)
                if (ssrc[s] >= 0)
                    *reinterpret_cast<uint4*>(sIn2 + sdst[s]) = pf[s];
        }

        // ---- GRU combine: out_off/out_mean + sOff ----
        for (int i = t; i < 18*64; i += 256) {
            int oc = i >> 6, px = i & 63;
            int idx = ((b*MH + oc)*HH + h)*WW + w0 + px;
            float cv = tanhf(so2[px*SO_PITCH + oc] + g_candx[idx] + ob[oc]);
            float u  = g_update[idx];
            float p  = pre[idx];
            float mn = 0.5f*(mean[idx] + p);
            float ofv = p*(1.f - u) + cv*u + mn;
            out_off[idx]  = ofv;
            out_mean[idx] = mn;
            sOff[px*20 + oc] = ofv;
        }
        __syncthreads();

        // ---- warp phase 0: offsets -> corner indices + weights ----
        for (int item = t; item < 576; item += 256) {
            int n = item >> 6, px = item & 63;
            int wc = w0 + px;
            float pnx = (float)(n/3 - 1), pny = (float)(n%3 - 1);
            float ox = sOff[px*20 + n];
            float oy = sOff[px*20 + 9 + n];
            float mm = g_m[((b*NN + n)*HH + h)*WW + wc];
            float px_ = (float)(h + 1) + pnx + ox;
            float py_ = (float)(wc + 1) + pny + oy;
            float fx = floorf(px_), fy = floorf(py_);
            float qxl = fminf(fmaxf(fx,       0.f), 129.f);
            float qxr = fminf(fmaxf(fx + 1.f, 0.f), 129.f);
            float qyl = fminf(fmaxf(fy,       0.f), 129.f);
            float qyr = fminf(fmaxf(fy + 1.f, 0.f), 129.f);
            float pxc = fminf(fmaxf(px_, 0.f), 129.f);
            float pyc = fminf(fmaxf(py_, 0.f), 129.f);
            float gx_l = 1.f + (qxl - pxc);
            float gx_r = 1.f - (qxr - pxc);
            float gy_l = 1.f + (qyl - pyc);
            float gy_r = 1.f - (qyr - pyc);
            int ixl = (int)qxl, ixr = (int)qxr, iyl = (int)qyl, iyr = (int)qyr;
            wts[item] = make_float4(gx_l*gy_l*mm, gx_r*gy_r*mm,
                                    gx_l*gy_r*mm, gx_r*gy_l*mm);
            ads[item] = make_int4(ixl*130 + iyl, ixr*130 + iyr,
                                  ixl*130 + iyr, ixr*130 + iyl);
        }
        __syncthreads();

        // ---- gather + blend -> sv fp16 ----
        #pragma unroll 2
        for (int p = 0; p < 18; ++p) {
            int item = p*32 + warp*4 + gg;
            int n = item >> 6, px = item & 63;
            float4 wt = wts[item];
            int4   ad = ads[item];
            uint4 rLT = *reinterpret_cast<const uint4*>(xh + ad.x*64 + cc8*8);
            uint4 rRB = *reinterpret_cast<const uint4*>(xh + ad.y*64 + cc8*8);
            uint4 rLB = *reinterpret_cast<const uint4*>(xh + ad.z*64 + cc8*8);
            uint4 rRT = *reinterpret_cast<const uint4*>(xh + ad.w*64 + cc8*8);
            ull dLT = dup2(wt.x), dRB = dup2(wt.y), dLB = dup2(wt.z), dRT = dup2(wt.w);
            uint32_t outh[4];
            const uint32_t* hLT = &rLT.x;
            const uint32_t* hRB = &rRB.x;
            const uint32_t* hLB = &rLB.x;
            const uint32_t* hRT = &rRT.x;
            #pragma unroll
            for (int q = 0; q < 4; ++q) {
                float2 fLT = __half22float2(*reinterpret_cast<const __half2*>(hLT + q));
                float2 fRB = __half22float2(*reinterpret_cast<const __half2*>(hRB + q));
                float2 fLB = __half22float2(*reinterpret_cast<const __half2*>(hLB + q));
                float2 fRT = __half22float2(*reinterpret_cast<const __half2*>(hRT + q));
                ull v;
                asm("mov.b64 %0,{%1,%2};" : "=l"(v) : "f"(fLT.x), "f"(fLT.y));
                v = fmul2(dLT, v);
                ull u2;
                asm("mov.b64 %0,{%1,%2};" : "=l"(u2) : "f"(fRB.x), "f"(fRB.y));
                v = ffma2(dRB, u2, v);
                asm("mov.b64 %0,{%1,%2};" : "=l"(u2) : "f"(fLB.x), "f"(fLB.y));
                v = ffma2(dLB, u2, v);
                asm("mov.b64 %0,{%1,%2};" : "=l"(u2) : "f"(fRT.x), "f"(fRT.y));
                v = ffma2(dRT, u2, v);
                float lo, hi;
                unpack2(v, lo, hi);
                __half2 hh = __floats2half2_rn(lo, hi);
                outh[q] = *reinterpret_cast<uint32_t*>(&hh);
            }
            *reinterpret_cast<uint4*>(sv + px*KP + n*64 + cc8*8) =
                make_uint4(outh[0], outh[1], outh[2], outh[3]);
        }
        __syncthreads();

        // ---- warp GEMM out[64px][64co] ----
        float d[4][4];
        #pragma unroll
        for (int i = 0; i < 4; ++i)
            #pragma unroll
            for (int j = 0; j < 4; ++j) d[i][j] = 0.f;

        #pragma unroll 4
        for (int ks = 0; ks < 36; ++ks) {
            uint32_t a0, a1, a2, a3, b0, b1, b2, b3, b4, b5, b6, b7;
            asm volatile("ldmatrix.sync.aligned.m8n8.x4.shared.b16 {%0,%1,%2,%3},[%4];"
                : "=r"(a0), "=r"(a1), "=r"(a2), "=r"(a3) : "r"(aAddr + ks*32));
            asm volatile("ldmatrix.sync.aligned.m8n8.x4.shared.b16 {%0,%1,%2,%3},[%4];"
                : "=r"(b0), "=r"(b1), "=r"(b2), "=r"(b3) : "r"(bAddr0 + ks*32));
            asm volatile("ldmatrix.sync.aligned.m8n8.x4.shared.b16 {%0,%1,%2,%3},[%4];"
                : "=r"(b4), "=r"(b5), "=r"(b6), "=r"(b7) : "r"(bAddr1 + ks*32));
            asm volatile("mma.sync.aligned.m16n8k16.row.col.f32.f16.f16.f32 "
                "{%0,%1,%2,%3},{%4,%5,%6,%7},{%8,%9},{%0,%1,%2,%3};"
                : "+f"(d[0][0]), "+f"(d[0][1]), "+f"(d[0][2]), "+f"(d[0][3])
                : "r"(a0), "r"(a1), "r"(a2), "r"(a3), "r"(b0), "r"(b1));
            asm volatile("mma.sync.aligned.m16n8k16.row.col.f32.f16.f16.f32 "
                "{%0,%1,%2,%3},{%4,%5,%6,%7},{%8,%9},{%0,%1,%2,%3};"
                : "+f"(d[1][0]), "+f"(d[1][1]), "+f"(d[1][2]), "+f"(d[1][3])
                : "r"(a0), "r"(a1), "r"(a2), "r"(a3), "r"(b2), "r"(b3));
            asm volatile("mma.sync.aligned.m16n8k16.row.col.f32.f16.f16.f32 "
                "{%0,%1,%2,%3},{%4,%5,%6,%7},{%8,%9},{%0,%1,%2,%3};"
                : "+f"(d[2][0]), "+f"(d[2][1]), "+f"(d[2][2]), "+f"(d[2][3])
                : "r"(a0), "r"(a1), "r"(a2), "r"(a3), "r"(b4), "r"(b5));
            asm volatile("mma.sync.aligned.m16n8k16.row.col.f32.f16.f16.f32 "
                "{%0,%1,%2,%3},{%4,%5,%6,%7},{%8,%9},{%0,%1,%2,%3};"
                : "+f"(d[3][0]), "+f"(d[3][1]), "+f"(d[3][2]), "+f"(d[3][3])
                : "r"(a0), "r"(a1), "r"(a2), "r"(a3), "r"(b6), "r"(b7));
        }
        __syncthreads();   // sv reads AND wts/ads reads complete

        #pragma unroll
        for (int nt = 0; nt < 4; ++nt) {
            int cb = co0w + nt*8 + tig*2;
            int pr = px0w + gid;
            so[pr*69 + cb]         = d[nt][0];
            so[pr*69 + cb + 1]     = d[nt][1];
            so[(pr+8)*69 + cb]     = d[nt][2];
            so[(pr+8)*69 + cb + 1] = d[nt][3];
        }
        __syncthreads();

        for (int i = t; i < 4096; i += 256) {
            int co = i >> 6, px = i & 63;
            out[((b*CC + co)*HH + h)*WW + w0 + px] = so[px*69 + co];
        }
        __syncthreads();   // scratch region free before next tile's so2 writes
    }
}

// ---------------- launch ----------------
extern "C" void kernel_launch(void* const* d_in, const int* in_sizes, int n_in,
                              void* d_out, int out_size)
{
    const float* x    = (const float*)d_in[0];
    const float* pre  = (const float*)d_in[1];
    const float* mean = (const float*)d_in[2];
    const float* uw   = (const float*)d_in[3];
    const float* ub   = (const float*)d_in[4];
    const float* rw   = (const float*)d_in[5];
    const float* rb   = (const float*)d_in[6];
    const float* ow   = (const float*)d_in[7];
    const float* ob   = (const float*)d_in[8];
    const float* ww   = (const float*)d_in[9];
    const float* wb   = (const float*)d_in[10];
    const float* wc   = (const float*)d_in[11];

    float* out_x    = (float*)d_out;
    float* out_off  = out_x + BB*CC*HH*WW;
    float* out_mean = out_off + BB*MH*HH*WW;

    cudaFuncSetAttribute(k1_gates, cudaFuncAttributeMaxDynamicSharedMemorySize, K1_SMEM);
    cudaFuncSetAttribute(k_fused,  cudaFuncAttributeMaxDynamicSharedMemorySize, F_SMEM);

    k_pad <<<dim3(4, 128, 4), dim3(32, 8)>>>(x);
    k_padp<<<dim3(HH, BB), 128>>>(pre);

    k1_gates<<<148, 256, K1_SMEM>>>(pre, uw, ub, rw, rb, ww, wb, ow);
    k_fused <<<148, 256, F_SMEM>>>(pre, mean, ow, ob, wc, out_off, out_mean, out_x);
}

// round 16
// speedup vs baseline: 1.0391x; 1.0391x over previous
#include <cuda_runtime.h>
#include <cuda_fp16.h>
#include <math.h>
#include <stdint.h>

#define BB 4
#define CC 64
#define MH 18
#define HH 128
#define WW 128
#define NN 9
#define HWX (HH*WW)

typedef unsigned long long ull;

// ---------------- scratch (static __device__, zero-initialized) ----------------
__device__ float  g_update[BB*MH*HH*WW];
__device__ float  g_m     [BB*NN*HH*WW];
__device__ float  g_candx [BB*MH*HH*WW];
__device__ __half g_xTh   [BB*130*130*CC];   // padded NHWC x (fp16); border stays 0
__device__ __half g_preh  [BB*130*130*24];   // padded NHWC pre (fp16, 18 used)
__device__ __half g_rgh   [BB*130*130*24];   // padded NHWC rgoff (fp16, 18 used)

__device__ __forceinline__ float sigf(float x) { return 1.f/(1.f + __expf(-x)); }

// ---- f32x2 helpers ----
__device__ __forceinline__ ull ffma2(ull a, ull b, ull c) {
    ull d; asm("fma.rn.f32x2 %0,%1,%2,%3;" : "=l"(d) : "l"(a), "l"(b), "l"(c)); return d;
}
__device__ __forceinline__ ull fmul2(ull a, ull b) {
    ull d; asm("mul.rn.f32x2 %0,%1,%2;" : "=l"(d) : "l"(a), "l"(b)); return d;
}
__device__ __forceinline__ ull dup2(float v) {
    ull d; asm("mov.b64 %0,{%1,%1};" : "=l"(d) : "f"(v)); return d;
}
__device__ __forceinline__ void unpack2(ull p, float& lo, float& hi) {
    asm("mov.b64 {%0,%1},%2;" : "=f"(lo), "=f"(hi) : "l"(p));
}
__device__ __forceinline__ uint32_t smaddr(const void* p) {
    return (uint32_t)__cvta_generic_to_shared(p);
}

// ---------------- kernel: NCHW fp32 x -> padded NHWC fp16 (interior) ----------------
__global__ void k_pad(const float* __restrict__ x) {
    __shared__ float sm[64][33];
    int jb = blockIdx.x, i0 = blockIdx.y, b = blockIdx.z;
    int tx = threadIdx.x, ty = threadIdx.y;
    int jcol = jb*32 + tx;
    for (int c = ty; c < 64; c += 8)
        sm[c][tx] = x[((b*CC + c)*HH + i0)*WW + jcol];
    __syncthreads();
    for (int jj = ty; jj < 32; jj += 8) {
        int base = ((b*130 + (i0+1))*130 + (jb*32 + jj + 1))*64;
        g_xTh[base + tx]      = __float2half_rn(sm[tx][jj]);
        g_xTh[base + 32 + tx] = __float2half_rn(sm[32 + tx][jj]);
    }
}

// ---------------- kernel: NCHW fp32 pre -> padded NHWC fp16 (interior) ----------------
__global__ void k_padp(const float* __restrict__ pre) {
    __shared__ float sm[18][129];
    int h = blockIdx.x, b = blockIdx.y;
    int t = threadIdx.x;
    #pragma unroll
    for (int c = 0; c < 18; ++c)
        sm[c][t] = pre[((b*MH + c)*HH + h)*WW + t];
    __syncthreads();
    __half* dst = g_preh + (size_t)((b*130 + h + 1)*130 + t + 1)*24;
    #pragma unroll
    for (int c = 0; c < 18; c += 2) {
        __half2 hh = __floats2half2_rn(sm[c][t], sm[c+1][t]);
        *reinterpret_cast<__half2*>(dst + c) = hh;
    }
}

// ====== shared HMMA conv geometry ======
#define PIN 104
#define SIN_ROWS 198
#define SIN_B (SIN_ROWS*PIN*2)
#define WPP 872
#define SO_PITCH 68
#define SO_B (64*SO_PITCH*4)
#define NTILES (BB*HH*2)

// ================= K1: upd + rst + wg + cand_x convs via HMMA =================
#define W1_OC 64
#define K1_SO_OFF (SIN_B + W1_OC*WPP*2)
#define K1_RG_OFF (K1_SO_OFF + SO_B)
#define K1_SMEM (K1_RG_OFF + 64*24*2)
#define K1_SLOTS 9

__global__ void __launch_bounds__(256, 1) k1_gates(
    const float* __restrict__ pre,
    const float* __restrict__ uw, const float* __restrict__ ub,
    const float* __restrict__ rw, const float* __restrict__ rb,
    const float* __restrict__ ww, const float* __restrict__ wb,
    const float* __restrict__ ow)
{
    extern __shared__ char shb[];
    __half* sIn = reinterpret_cast<__half*>(shb);
    __half* Wp  = reinterpret_cast<__half*>(shb + SIN_B);
    float*  so  = reinterpret_cast<float*>(shb + K1_SO_OFF);
    __half* sRg = reinterpret_cast<__half*>(shb + K1_RG_OFF);

    int t = threadIdx.x;
    int lane = t & 31, warp = t >> 5;

    for (int i = t; i < SIN_ROWS*PIN/8; i += 256)
        reinterpret_cast<uint4*>(sIn)[i] = make_uint4(0,0,0,0);
    for (int i = t; i < W1_OC*WPP/8; i += 256)
        reinterpret_cast<uint4*>(Wp)[i] = make_uint4(0,0,0,0);
    for (int i = t; i < 64*24/8; i += 256)
        reinterpret_cast<uint4*>(sRg)[i] = make_uint4(0,0,0,0);
    __syncthreads();
    for (int i = t; i < 18*738; i += 256) {
        int oc = i / 738, r = i % 738, ic = r / 9, pos = r % 9;
        Wp[oc*WPP + pos*96 + ic]        = __float2half_rn(uw[i]);
        Wp[(18 + oc)*WPP + pos*96 + ic] = __float2half_rn(rw[i]);
    }
    for (int i = t; i < 9*576; i += 256) {
        int oc = i / 576, r = i % 576, ic = r / 9, pos = r % 9;
        Wp[(36 + oc)*WPP + pos*96 + ic] = __float2half_rn(ww[i]);
    }
    for (int i = t; i < 18*576; i += 256) {
        int oc = i / 576, r = i % 576, ic = r / 9, pos = r % 9;
        Wp[(45 + oc)*WPP + pos*96 + ic] = __float2half_rn(ow[oc*738 + ic*9 + pos]);
    }
    __syncthreads();

    int ssrc[K1_SLOTS], sdst[K1_SLOTS], skind[K1_SLOTS];
    #pragma unroll
    for (int s = 0; s < K1_SLOTS; ++s) {
        int e = t + s*256;
        if (e < 2178) {
            int r = e / 11, u = e % 11;
            int crow = r / 66, col = r % 66;
            if (u < 8) {
                skind[s] = 0;
                ssrc[s] = (crow*130 + col)*64 + u*8;
                sdst[s] = r*PIN + u*8;
            } else {
                skind[s] = 1;
                ssrc[s] = (crow*130 + col)*24 + (u - 8)*8;
                sdst[s] = r*PIN + 64 + (u - 8)*8;
            }
        } else skind[s] = -1;
    }

    {
        int tile = blockIdx.x;
        int b = tile >> 8, rem = tile & 255;
        int h = rem >> 1, w0 = (rem & 1) << 6;
        const __half* xb = g_xTh  + (size_t)((b*130 + h)*130 + w0)*64;
        const __half* pb = g_preh + (size_t)((b*130 + h)*130 + w0)*24;
        #pragma unroll
        for (int s = 0; s < K1_SLOTS; ++s) {
            if (skind[s] == 0)
                *reinterpret_cast<uint4*>(sIn + sdst[s]) =
                    *reinterpret_cast<const uint4*>(xb + ssrc[s]);
            else if (skind[s] == 1)
                *reinterpret_cast<uint4*>(sIn + sdst[s]) =
                    *reinterpret_cast<const uint4*>(pb + ssrc[s]);
        }
    }
    __syncthreads();

    int wp = warp & 3, wo = warp >> 2;
    int px0 = wp * 16, oc0 = wo * 32;
    uint32_t aBase = smaddr(sIn) + (((px0 + (lane & 15))*PIN) + (lane >> 4)*8)*2;
    uint32_t bBase = smaddr(Wp) + ((oc0 + (lane & 7) + ((lane >> 4) & 1)*8)*WPP)*2
                     + ((lane >> 3) & 1)*16;
    int gid = lane >> 2, tig = lane & 3;

    for (int tile = blockIdx.x; tile < NTILES; tile += gridDim.x) {
        int b = tile >> 8;
        int rem = tile & 255;
        int h  = rem >> 1;
        int w0 = (rem & 1) << 6;

        int nxt = tile + gridDim.x;
        bool hasNext = nxt < NTILES;
        uint4 pf[K1_SLOTS];
        if (hasNext) {
            int b2 = nxt >> 8, rem2 = nxt & 255;
            int h2 = rem2 >> 1, w02 = (rem2 & 1) << 6;
            const __half* xb2 = g_xTh  + (size_t)((b2*130 + h2)*130 + w02)*64;
            const __half* pb2 = g_preh + (size_t)((b2*130 + h2)*130 + w02)*24;
            #pragma unroll
            for (int s = 0; s < K1_SLOTS; ++s) {
                if (skind[s] == 0)
                    pf[s] = *reinterpret_cast<const uint4*>(xb2 + ssrc[s]);
                else if (skind[s] == 1)
                    pf[s] = *reinterpret_cast<const uint4*>(pb2 + ssrc[s]);
            }
        }

        float d[4][4];
        #pragma unroll
        for (int i = 0; i < 4; ++i)
            #pragma unroll
            for (int j = 0; j < 4; ++j) d[i][j] = 0.f;

        #pragma unroll 1
        for (int pos = 0; pos < 9; ++pos) {
            int ki = pos / 3, kj = pos % 3;
            uint32_t aPos = aBase + (ki*66 + kj)*PIN*2;
            uint32_t bPos = bBase + pos*96*2;
            #pragma unroll
            for (int kk = 0; kk < 6; ++kk) {
                uint32_t a0,a1,a2,a3, b0,b1,b2,b3, b4,b5,b6,b7;
                asm volatile("ldmatrix.sync.aligned.m8n8.x4.shared.b16 {%0,%1,%2,%3},[%4];"
                    : "=r"(a0),"=r"(a1),"=r"(a2),"=r"(a3) : "r"(aPos + kk*32));
                asm volatile("ldmatrix.sync.aligned.m8n8.x4.shared.b16 {%0,%1,%2,%3},[%4];"
                    : "=r"(b0),"=r"(b1),"=r"(b2),"=r"(b3) : "r"(bPos + kk*32));
                asm volatile("ldmatrix.sync.aligned.m8n8.x4.shared.b16 {%0,%1,%2,%3},[%4];"
                    : "=r"(b4),"=r"(b5),"=r"(b6),"=r"(b7) : "r"(bPos + 16*WPP*2 + kk*32));
                asm volatile("mma.sync.aligned.m16n8k16.row.col.f32.f16.f16.f32 "
                    "{%0,%1,%2,%3},{%4,%5,%6,%7},{%8,%9},{%0,%1,%2,%3};"
                    : "+f"(d[0][0]),"+f"(d[0][1]),"+f"(d[0][2]),"+f"(d[0][3])
                    : "r"(a0),"r"(a1),"r"(a2),"r"(a3),"r"(b0),"r"(b1));
                asm volatile("mma.sync.aligned.m16n8k16.row.col.f32.f16.f16.f32 "
                    "{%0,%1,%2,%3},{%4,%5,%6,%7},{%8,%9},{%0,%1,%2,%3};"
                    : "+f"(d[1][0]),"+f"(d[1][1]),"+f"(d[1][2]),"+f"(d[1][3])
                    : "r"(a0),"r"(a1),"r"(a2),"r"(a3),"r"(b2),"r"(b3));
                asm volatile("mma.sync.aligned.m16n8k16.row.col.f32.f16.f16.f32 "
                    "{%0,%1,%2,%3},{%4,%5,%6,%7},{%8,%9},{%0,%1,%2,%3};"
                    : "+f"(d[2][0]),"+f"(d[2][1]),"+f"(d[2][2]),"+f"(d[2][3])
                    : "r"(a0),"r"(a1),"r"(a2),"r"(a3),"r"(b4),"r"(b5));
                asm volatile("mma.sync.aligned.m16n8k16.row.col.f32.f16.f16.f32 "
                    "{%0,%1,%2,%3},{%4,%5,%6,%7},{%8,%9},{%0,%1,%2,%3};"
                    : "+f"(d[3][0]),"+f"(d[3][1]),"+f"(d[3][2]),"+f"(d[3][3])
                    : "r"(a0),"r"(a1),"r"(a2),"r"(a3),"r"(b6),"r"(b7));
            }
        }

        #pragma unroll
        for (int nt = 0; nt < 4; ++nt) {
            int oc = oc0 + nt*8 + tig*2;
            int pr = px0 + gid;
            so[pr*SO_PITCH + oc]         = d[nt][0];
            so[pr*SO_PITCH + oc + 1]     = d[nt][1];
            so[(pr+8)*SO_PITCH + oc]     = d[nt][2];
            so[(pr+8)*SO_PITCH + oc + 1] = d[nt][3];
        }
        __syncthreads();

        if (hasNext) {
            #pragma unroll
            for (int s = 0; s < K1_SLOTS; ++s)
                if (skind[s] >= 0)
                    *reinterpret_cast<uint4*>(sIn + sdst[s]) = pf[s];
        }

        for (int i = t; i < 63*64; i += 256) {
            int oc = i >> 6, px = i & 63;
            float a = so[px*SO_PITCH + oc];
            if (oc < 18) {
                g_update[((b*MH + oc)*HH + h)*WW + w0 + px] = sigf(a + ub[oc]);
            } else if (oc < 36) {
                int o = oc - 18;
                int idx = ((b*MH + o)*HH + h)*WW + w0 + px;
                float rv = pre[idx] * sigf(a + rb[o]);
                sRg[px*24 + o] = __float2half_rn(rv);
            } else if (oc < 45) {
                int o = oc - 36;
                g_m[((b*NN + o)*HH + h)*WW + w0 + px] = sigf(a + wb[o]);
            } else {
                int o = oc - 45;
                g_candx[((b*MH + o)*HH + h)*WW + w0 + px] = a;
            }
        }
        __syncthreads();

        {
            __half* dst = g_rgh + (size_t)((b*130 + h + 1)*130 + (w0 + 1))*24;
            if (t < 192)
                reinterpret_cast<uint4*>(dst)[t] =
                    reinterpret_cast<const uint4*>(sRg)[t];
        }
    }
}

// ================= K2: cand_p conv (K=18->32) + GRU combine =================
#define PIN2 40
#define SIN2_B (SIN_ROWS*PIN2*2)
#define WPP2 296
#define W2_OC 32
#define K2_SO_OFF (SIN2_B + W2_OC*WPP2*2)
#define K2_SMEM (K2_SO_OFF + SO_B)
#define K2_SLOTS 3

__global__ void __launch_bounds__(256, 2) k2_cand(
    const float* __restrict__ pre, const float* __restrict__ mean,
    const float* __restrict__ ow, const float* __restrict__ ob,
    float* __restrict__ out_off, float* __restrict__ out_mean)
{
    extern __shared__ char shb[];
    __half* sIn = reinterpret_cast<__half*>(shb);
    __half* Wp  = reinterpret_cast<__half*>(shb + SIN2_B);
    float*  so  = reinterpret_cast<float*>(shb + K2_SO_OFF);

    int t = threadIdx.x;
    int lane = t & 31, warp = t >> 5;

    for (int i = t; i < SIN_ROWS*PIN2/8; i += 256)
        reinterpret_cast<uint4*>(sIn)[i] = make_uint4(0,0,0,0);
    for (int i = t; i < W2_OC*WPP2/8; i += 256)
        reinterpret_cast<uint4*>(Wp)[i] = make_uint4(0,0,0,0);
    __syncthreads();
    for (int i = t; i < 18*162; i += 256) {
        int oc = i / 162, r = i % 162, icp = r / 9, pos = r % 9;
        Wp[oc*WPP2 + pos*32 + icp] = __float2half_rn(ow[oc*738 + (64 + icp)*9 + pos]);
    }
    __syncthreads();

    int ssrc[K2_SLOTS], sdst[K2_SLOTS];
    #pragma unroll
    for (int s = 0; s < K2_SLOTS; ++s) {
        int e = t + s*256;
        if (e < 594) {
            int r = e / 3, u = e % 3;
            int crow = r / 66, col = r % 66;
            ssrc[s] = (crow*130 + col)*24 + u*8;
            sdst[s] = r*PIN2 + u*8;
        } else { ssrc[s] = -1; sdst[s] = 0; }
    }

    {
        int tile = blockIdx.x;
        if (tile < NTILES) {
            int b = tile >> 8, rem = tile & 255;
            int h = rem >> 1, w0 = (rem & 1) << 6;
            const __half* rb2 = g_rgh + (size_t)((b*130 + h)*130 + w0)*24;
            #pragma unroll
            for (int s = 0; s < K2_SLOTS; ++s)
                if (ssrc[s] >= 0)
                    *reinterpret_cast<uint4*>(sIn + sdst[s]) =
                        *reinterpret_cast<const uint4*>(rb2 + ssrc[s]);
        }
    }
    __syncthreads();

    int wp = warp & 3, wo = warp >> 2;
    int px0 = wp * 16, oc0 = wo * 16;
    uint32_t aBase = smaddr(sIn) + (((px0 + (lane & 15))*PIN2) + (lane >> 4)*8)*2;
    uint32_t bBase = smaddr(Wp) + ((oc0 + (lane & 7) + ((lane >> 4) & 1)*8)*WPP2)*2
                     + ((lane >> 3) & 1)*16;
    int gid = lane >> 2, tig = lane & 3;

    for (int tile = blockIdx.x; tile < NTILES; tile += gridDim.x) {
        int b = tile >> 8;
        int rem = tile & 255;
        int h  = rem >> 1;
        int w0 = (rem & 1) << 6;

        int nxt = tile + gridDim.x;
        bool hasNext = nxt < NTILES;
        uint4 pf[K2_SLOTS];
        if (hasNext) {
            int b2 = nxt >> 8, rem2 = nxt & 255;
            int h2 = rem2 >> 1, w02 = (rem2 & 1) << 6;
            const __half* rb2 = g_rgh + (size_t)((b2*130 + h2)*130 + w02)*24;
            #pragma unroll
            for (int s = 0; s < K2_SLOTS; ++s)
                if (ssrc[s] >= 0)
                    pf[s] = *reinterpret_cast<const uint4*>(rb2 + ssrc[s]);
        }

        float d[2][4];
        #pragma unroll
        for (int i = 0; i < 2; ++i)
            #pragma unroll
            for (int j = 0; j < 4; ++j) d[i][j] = 0.f;

        #pragma unroll 1
        for (int pos = 0; pos < 9; ++pos) {
            int ki = pos / 3, kj = pos % 3;
            uint32_t aPos = aBase + (ki*66 + kj)*PIN2*2;
            uint32_t bPos = bBase + pos*32*2;
            #pragma unroll
            for (int kk = 0; kk < 2; ++kk) {
                uint32_t a0,a1,a2,a3, b0,b1,b2,b3;
                asm volatile("ldmatrix.sync.aligned.m8n8.x4.shared.b16 {%0,%1,%2,%3},[%4];"
                    : "=r"(a0),"=r"(a1),"=r"(a2),"=r"(a3) : "r"(aPos + kk*32));
                asm volatile("ldmatrix.sync.aligned.m8n8.x4.shared.b16 {%0,%1,%2,%3},[%4];"
                    : "=r"(b0),"=r"(b1),"=r"(b2),"=r"(b3) : "r"(bPos + kk*32));
                asm volatile("mma.sync.aligned.m16n8k16.row.col.f32.f16.f16.f32 "
                    "{%0,%1,%2,%3},{%4,%5,%6,%7},{%8,%9},{%0,%1,%2,%3};"
                    : "+f"(d[0][0]),"+f"(d[0][1]),"+f"(d[0][2]),"+f"(d[0][3])
                    : "r"(a0),"r"(a1),"r"(a2),"r"(a3),"r"(b0),"r"(b1));
                asm volatile("mma.sync.aligned.m16n8k16.row.col.f32.f16.f16.f32 "
                    "{%0,%1,%2,%3},{%4,%5,%6,%7},{%8,%9},{%0,%1,%2,%3};"
                    : "+f"(d[1][0]),"+f"(d[1][1]),"+f"(d[1][2]),"+f"(d[1][3])
                    : "r"(a0),"r"(a1),"r"(a2),"r"(a3),"r"(b2),"r"(b3));
            }
        }

        #pragma unroll
        for (int nt = 0; nt < 2; ++nt) {
            int oc = oc0 + nt*8 + tig*2;
            int pr = px0 + gid;
            so[pr*SO_PITCH + oc]         = d[nt][0];
            so[pr*SO_PITCH + oc + 1]     = d[nt][1];
            so[(pr+8)*SO_PITCH + oc]     = d[nt][2];
            so[(pr+8)*SO_PITCH + oc + 1] = d[nt][3];
        }
        __syncthreads();

        if (hasNext) {
            #pragma unroll
            for (int s = 0; s < K2_SLOTS; ++s)
                if (ssrc[s] >= 0)
                    *reinterpret_cast<uint4*>(sIn + sdst[s]) = pf[s];
        }

        for (int i = t; i < 18*64; i += 256) {
            int oc = i >> 6, px = i & 63;
            int idx = ((b*MH + oc)*HH + h)*WW + w0 + px;
            float cv = tanhf(so[px*SO_PITCH + oc] + g_candx[idx] + ob[oc]);
            float u  = g_update[idx];
            float p  = pre[idx];
            float mn = 0.5f*(mean[idx] + p);
            out_off[idx]  = p*(1.f - u) + cv*u + mn;
            out_mean[idx] = mn;
        }
        __syncthreads();
    }
}

// ================= k_warp: deformable warp + regroup conv via HMMA =================
#define KP 584
#define W_SW_OFF 0
#define W_SV_OFF (64*KP*2)
#define W_WT_OFF (W_SV_OFF + 64*KP*2)
#define W_AD_OFF (W_WT_OFF + 576*16)
#define W_SMEMB (W_AD_OFF + 576*16)

__global__ void __launch_bounds__(256, 1) k_warp(
    const float* __restrict__ off, const float* __restrict__ Wc,
    float* __restrict__ out)
{
    extern __shared__ char shb[];
    __half* sW  = reinterpret_cast<__half*>(shb + W_SW_OFF);
    __half* sv  = reinterpret_cast<__half*>(shb + W_SV_OFF);
    float4* wts = reinterpret_cast<float4*>(shb + W_WT_OFF);
    int4*   ads = reinterpret_cast<int4*>(shb + W_AD_OFF);
    float*  so  = reinterpret_cast<float*>(shb + W_WT_OFF);

    int t = threadIdx.x;
    int lane = t & 31, warp = t >> 5;

    for (int i = t; i < 64*576; i += 256) {
        int co = i / 576, r = i % 576;
        int ci = r / 9, n = r % 9;
        sW[co*KP + n*64 + ci] = __float2half_rn(Wc[i]);
    }
    __syncthreads();

    int gid = lane >> 2, tig = lane & 3;
    int px0 = (warp >> 1) * 16;
    int co0 = (warp & 1) * 32;
    uint32_t aAddr = smaddr(sv) + (((px0 + (lane & 15))*KP + (lane >> 4)*8) << 1);
    uint32_t bAddr0 = smaddr(sW) + (((co0 + (lane & 7) + (lane >> 4)*8)*KP
                                    + ((lane >> 3) & 1)*8) << 1);
    uint32_t bAddr1 = bAddr0 + 16*KP*2;

    int g = lane >> 3;
    int c = lane & 7;

    // phase-0 item slots (tile-invariant): item = t + s*256, s < 3
    int itn[3], itpx[3];
    bool itv[3];
    #pragma unroll
    for (int s = 0; s < 3; ++s) {
        int item = t + s*256;
        itv[s]  = item < 576;
        itn[s]  = (item >> 6) & 15;
        itpx[s] = item & 63;
    }

    // registers holding prefetched off/m for the CURRENT tile
    float pox[3], poy[3], pom[3];

    auto loadPh0 = [&](int tile) {
        int b = tile >> 8, rem = tile & 255;
        int h = rem >> 1, w0 = (rem & 1) << 6;
        #pragma unroll
        for (int s = 0; s < 3; ++s) {
            if (itv[s]) {
                int n = itn[s], wc = w0 + itpx[s];
                pox[s] = __ldg(off + ((b*MH + n    )*HH + h)*WW + wc);
                poy[s] = __ldg(off + ((b*MH + 9 + n)*HH + h)*WW + wc);
                pom[s] = __ldg(g_m + ((b*NN + n)*HH + h)*WW + wc);
            }
        }
    };

    loadPh0(blockIdx.x);

    for (int tile = blockIdx.x; tile < NTILES; tile += gridDim.x) {
        int b = tile >> 8;
        int rem = tile & 255;
        int h  = rem >> 1;
        int w0 = (rem & 1) << 6;
        const __half* xh = g_xTh + (size_t)b*130*130*64;

        // ---- phase 0 (ALU only; inputs already in registers) ----
        #pragma unroll
        for (int s = 0; s < 3; ++s) {
            if (itv[s]) {
                int item = t + s*256;
                int n = itn[s], px = itpx[s];
                int wc = w0 + px;
                float pnx = (float)(n/3 - 1), pny = (float)(n%3 - 1);
                float px_ = (float)(h + 1) + pnx + pox[s];
                float py_ = (float)(wc + 1) + pny + poy[s];
                float fx = floorf(px_), fy = floorf(py_);
                float qxl = fminf(fmaxf(fx,       0.f), 129.f);
                float qxr = fminf(fmaxf(fx + 1.f, 0.f), 129.f);
                float qyl = fminf(fmaxf(fy,       0.f), 129.f);
                float qyr = fminf(fmaxf(fy + 1.f, 0.f), 129.f);
                float pxc = fminf(fmaxf(px_, 0.f), 129.f);
                float pyc = fminf(fmaxf(py_, 0.f), 129.f);
                float gx_l = 1.f + (qxl - pxc);
                float gx_r = 1.f - (qxr - pxc);
                float gy_l = 1.f + (qyl - pyc);
                float gy_r = 1.f - (qyr - pyc);
                float mm = pom[s];
                int ixl = (int)qxl, ixr = (int)qxr, iyl = (int)qyl, iyr = (int)qyr;
                wts[item] = make_float4(gx_l*gy_l*mm, gx_r*gy_r*mm,
                                        gx_l*gy_r*mm, gx_r*gy_l*mm);
                ads[item] = make_int4(ixl*130 + iyl, ixr*130 + iyr,
                                      ixl*130 + iyr, ixr*130 + iyl);
            }
        }
        __syncthreads();

        // ---- gather + blend -> sv fp16 ----
        #pragma unroll 2
        for (int p = 0; p < 18; ++p) {
            int item = p*32 + warp*4 + g;
            int n = item >> 6, px = item & 63;
            float4 wt = wts[item];
            int4   ad = ads[item];
            uint4 rLT = *reinterpret_cast<const uint4*>(xh + ad.x*64 + c*8);
            uint4 rRB = *reinterpret_cast<const uint4*>(xh + ad.y*64 + c*8);
            uint4 rLB = *reinterpret_cast<const uint4*>(xh + ad.z*64 + c*8);
            uint4 rRT = *reinterpret_cast<const uint4*>(xh + ad.w*64 + c*8);
            ull dLT = dup2(wt.x), dRB = dup2(wt.y), dLB = dup2(wt.z), dRT = dup2(wt.w);
            uint32_t outh[4];
            const uint32_t* hLT = &rLT.x;
            const uint32_t* hRB = &rRB.x;
            const uint32_t* hLB = &rLB.x;
            const uint32_t* hRT = &rRT.x;
            #pragma unroll
            for (int q = 0; q < 4; ++q) {
                float2 fLT = __half22float2(*reinterpret_cast<const __half2*>(hLT + q));
                float2 fRB = __half22float2(*reinterpret_cast<const __half2*>(hRB + q));
                float2 fLB = __half22float2(*reinterpret_cast<const __half2*>(hLB + q));
                float2 fRT = __half22float2(*reinterpret_cast<const __half2*>(hRT + q));
                ull v;
                asm("mov.b64 %0,{%1,%2};" : "=l"(v) : "f"(fLT.x), "f"(fLT.y));
                v = fmul2(dLT, v);
                ull u2;
                asm("mov.b64 %0,{%1,%2};" : "=l"(u2) : "f"(fRB.x), "f"(fRB.y));
                v = ffma2(dRB, u2, v);
                asm("mov.b64 %0,{%1,%2};" : "=l"(u2) : "f"(fLB.x), "f"(fLB.y));
                v = ffma2(dLB, u2, v);
                asm("mov.b64 %0,{%1,%2};" : "=l"(u2) : "f"(fRT.x), "f"(fRT.y));
                v = ffma2(dRT, u2, v);
                float lo, hi;
                unpack2(v, lo, hi);
                __half2 hh = __floats2half2_rn(lo, hi);
                outh[q] = *reinterpret_cast<uint32_t*>(&hh);
            }
            *reinterpret_cast<uint4*>(sv + px*KP + n*64 + c*8) =
                make_uint4(outh[0], outh[1], outh[2], outh[3]);
        }
        __syncthreads();

        // issue next tile's phase-0 loads (fly during GEMM + writeout)
        int nxt = tile + gridDim.x;
        if (nxt < NTILES) loadPh0(nxt);

        float d[4][4];
        #pragma unroll
        for (int i = 0; i < 4; ++i)
            #pragma unroll
            for (int j = 0; j < 4; ++j) d[i][j] = 0.f;

        #pragma unroll 4
        for (int ks = 0; ks < 36; ++ks) {
            uint32_t a0, a1, a2, a3, b0, b1, b2, b3, b4, b5, b6, b7;
            asm volatile("ldmatrix.sync.aligned.m8n8.x4.shared.b16 {%0,%1,%2,%3},[%4];"
                : "=r"(a0), "=r"(a1), "=r"(a2), "=r"(a3) : "r"(aAddr + ks*32));
            asm volatile("ldmatrix.sync.aligned.m8n8.x4.shared.b16 {%0,%1,%2,%3},[%4];"
                : "=r"(b0), "=r"(b1), "=r"(b2), "=r"(b3) : "r"(bAddr0 + ks*32));
            asm volatile("ldmatrix.sync.aligned.m8n8.x4.shared.b16 {%0,%1,%2,%3},[%4];"
                : "=r"(b4), "=r"(b5), "=r"(b6), "=r"(b7) : "r"(bAddr1 + ks*32));
            asm volatile("mma.sync.aligned.m16n8k16.row.col.f32.f16.f16.f32 "
                "{%0,%1,%2,%3},{%4,%5,%6,%7},{%8,%9},{%0,%1,%2,%3};"
                : "+f"(d[0][0]), "+f"(d[0][1]), "+f"(d[0][2]), "+f"(d[0][3])
                : "r"(a0), "r"(a1), "r"(a2), "r"(a3), "r"(b0), "r"(b1));
            asm volatile("mma.sync.aligned.m16n8k16.row.col.f32.f16.f16.f32 "
                "{%0,%1,%2,%3},{%4,%5,%6,%7},{%8,%9},{%0,%1,%2,%3};"
                : "+f"(d[1][0]), "+f"(d[1][1]), "+f"(d[1][2]), "+f"(d[1][3])
                : "r"(a0), "r"(a1), "r"(a2), "r"(a3), "r"(b2), "r"(b3));
            asm volatile("mma.sync.aligned.m16n8k16.row.col.f32.f16.f16.f32 "
                "{%0,%1,%2,%3},{%4,%5,%6,%7},{%8,%9},{%0,%1,%2,%3};"
                : "+f"(d[2][0]), "+f"(d[2][1]), "+f"(d[2][2]), "+f"(d[2][3])
                : "r"(a0), "r"(a1), "r"(a2), "r"(a3), "r"(b4), "r"(b5));
            asm volatile("mma.sync.aligned.m16n8k16.row.col.f32.f16.f16.f32 "
                "{%0,%1,%2,%3},{%4,%5,%6,%7},{%8,%9},{%0,%1,%2,%3};"
                : "+f"(d[3][0]), "+f"(d[3][1]), "+f"(d[3][2]), "+f"(d[3][3])
                : "r"(a0), "r"(a1), "r"(a2), "r"(a3), "r"(b6), "r"(b7));
        }
        __syncthreads();

        #pragma unroll
        for (int nt = 0; nt < 4; ++nt) {
            int cb = co0 + nt*8 + tig*2;
            int pr = px0 + gid;
            so[pr*69 + cb]         = d[nt][0];
            so[pr*69 + cb + 1]     = d[nt][1];
            so[(pr+8)*69 + cb]     = d[nt][2];
            so[(pr+8)*69 + cb + 1] = d[nt][3];
        }
        __syncthreads();

        for (int i = t; i < 4096; i += 256) {
            int co = i >> 6, px = i & 63;
            out[((b*CC + co)*HH + h)*WW + w0 + px] = so[px*69 + co];
        }
        __syncthreads();
    }
}

// ---------------- launch ----------------
extern "C" void kernel_launch(void* const* d_in, const int* in_sizes, int n_in,
                              void* d_out, int out_size)
{
    const float* x    = (const float*)d_in[0];
    const float* pre  = (const float*)d_in[1];
    const float* mean = (const float*)d_in[2];
    const float* uw   = (const float*)d_in[3];
    const float* ub   = (const float*)d_in[4];
    const float* rw   = (const float*)d_in[5];
    const float* rb   = (const float*)d_in[6];
    const float* ow   = (const float*)d_in[7];
    const float* ob   = (const float*)d_in[8];
    const float* ww   = (const float*)d_in[9];
    const float* wb   = (const float*)d_in[10];
    const float* wc   = (const float*)d_in[11];

    float* out_x    = (float*)d_out;
    float* out_off  = out_x + BB*CC*HH*WW;
    float* out_mean = out_off + BB*MH*HH*WW;

    cudaFuncSetAttribute(k1_gates, cudaFuncAttributeMaxDynamicSharedMemorySize, K1_SMEM);
    cudaFuncSetAttribute(k2_cand,  cudaFuncAttributeMaxDynamicSharedMemorySize, K2_SMEM);
    cudaFuncSetAttribute(k_warp,   cudaFuncAttributeMaxDynamicSharedMemorySize, W_SMEMB);

    k_pad <<<dim3(4, 128, 4), dim3(32, 8)>>>(x);
    k_padp<<<dim3(HH, BB), 128>>>(pre);

    k1_gates<<<148, 256, K1_SMEM>>>(pre, uw, ub, rw, rb, ww, wb, ow);
    k2_cand <<<296, 256, K2_SMEM>>>(pre, mean, ow, ob, out_off, out_mean);
    k_warp  <<<148, 256, W_SMEMB>>>(out_off, wc, out_x);
}